// round 15
// baseline (speedup 1.0000x reference)
#include <cuda_runtime.h>
#include <cuda_fp16.h>
#include <cstdint>

#define NN 8192
#define FD 128
#define ALPHA 0.2f

__device__ float  g_Wa1[FD], g_Wa2[FD];
__device__ float  g_es[NN], g_ed[NN];
__device__ unsigned g_maxu;
__device__ uint32_t g_AAh2[NN], g_BBh2[NN];   // {A,A}, {B,B} half2
__device__ uint4  g_j4[NN / 4];               // {F01,G01,F23,G23} half2 x4
__device__ __half g_W16T[FD * FD];            // [fo][k]
__device__ __half g_WhT[(size_t)FD * NN];     // [f][node]
__device__ float  g_part[2u * NN * FD];
__device__ float  g_lsp[2 * NN];
__device__ int    g_cnt[64];

__device__ __forceinline__ float leakyf(float x) { return fmaxf(x, ALPHA * x); }
__device__ __forceinline__ uint32_t packh2(float x, float y) {
    __half2 h = __floats2half2_rn(x, y);
    return reinterpret_cast<uint32_t&>(h);
}
__device__ __forceinline__ __half2 u2h(uint32_t u) { return *reinterpret_cast<__half2*>(&u); }
__device__ __forceinline__ uint32_t h2u(__half2 h) { return *reinterpret_cast<uint32_t*>(&h); }
__device__ __forceinline__ void mma16816(float* c,
                                         uint32_t a0, uint32_t a1, uint32_t a2, uint32_t a3,
                                         uint32_t b0, uint32_t b1) {
    asm volatile(
        "mma.sync.aligned.m16n8k16.row.col.f32.f16.f16.f32 "
        "{%0,%1,%2,%3}, {%4,%5,%6,%7}, {%8,%9}, {%0,%1,%2,%3};\n"
        : "+f"(c[0]), "+f"(c[1]), "+f"(c[2]), "+f"(c[3])
        : "r"(a0), "r"(a1), "r"(a2), "r"(a3), "r"(b0), "r"(b1));
}
__device__ __forceinline__ void cp16(void* s, const void* g) {
    unsigned sa = (unsigned)__cvta_generic_to_shared(s);
    asm volatile("cp.async.cg.shared.global [%0], [%1], 16;\n" :: "r"(sa), "l"(g));
}
__device__ __forceinline__ void ldm4(uint32_t* r, uint32_t a) {
    asm volatile("ldmatrix.sync.aligned.m8n8.x4.shared.b16 {%0,%1,%2,%3}, [%4];"
                 : "=r"(r[0]), "=r"(r[1]), "=r"(r[2]), "=r"(r[3]) : "r"(a));
}
__device__ __forceinline__ unsigned fenc(float f) {
    unsigned b = __float_as_uint(f);
    return (b & 0x80000000u) ? ~b : (b | 0x80000000u);
}
__device__ __forceinline__ float fdec(unsigned k) {
    unsigned b = (k & 0x80000000u) ? (k & 0x7FFFFFFFu) : ~k;
    return __uint_as_float(b);
}

// ---- k_init: Wa1/Wa2, W fp16 transpose, reset max + counters ----------------
__global__ void k_init(const float* __restrict__ W, const float* __restrict__ a) {
    if (blockIdx.x == 0) {
        int i = threadIdx.x;
        if (i == 0) g_maxu = 0u;
        if (i < 64) g_cnt[i] = 0;
        if (i < FD) {
            const float* wr = W + i * FD;
            float s1 = 0.f, s2 = 0.f;
#pragma unroll 8
            for (int j = 0; j < FD; ++j) {
                float w = wr[j];
                s1 += w * a[j];
                s2 += w * a[FD + j];
            }
            g_Wa1[i] = s1; g_Wa2[i] = s2;
        }
    } else {
        int n = (blockIdx.x - 1) * 256 + threadIdx.x;
        int k = n >> 7, fo = n & 127;
        g_W16T[fo * FD + k] = __float2half(W[n]);
    }
}

// ---- k_esd: es/ed exact fp32 GEMV + fused global max ------------------------
__global__ void __launch_bounds__(256) k_esd(const float* __restrict__ h) {
    __shared__ float s1[FD], s2[FD];
    int t = threadIdx.x, l = t & 31, w = t >> 5;
    if (t < FD) { s1[t] = g_Wa1[t]; s2[t] = g_Wa2[t]; }
    __syncthreads();
    int i = blockIdx.x * 8 + w;
    float4 hv0 = *(const float4*)(h + (size_t)i * FD + l * 4);
    float e1 = hv0.x*s1[l*4] + hv0.y*s1[l*4+1] + hv0.z*s1[l*4+2] + hv0.w*s1[l*4+3];
    float e2 = hv0.x*s2[l*4] + hv0.y*s2[l*4+1] + hv0.z*s2[l*4+2] + hv0.w*s2[l*4+3];
#pragma unroll
    for (int o = 16; o; o >>= 1) {
        e1 += __shfl_xor_sync(0xffffffffu, e1, o);
        e2 += __shfl_xor_sync(0xffffffffu, e2, o);
    }
    if (l == 0) {
        g_es[i] = e1; g_ed[i] = e2;
        atomicMax(&g_maxu, fenc(e2));
    }
}

// ---- k_wh16: fused pre (AA/BB/j4) + WhT = (h@W)^T fp16 via HMMA -------------
#define PITCH 272
__global__ void __launch_bounds__(256) k_wh16(const float* __restrict__ h) {
    __shared__ __align__(16) char sb[128 * PITCH + 64 * PITCH];
    __shared__ float sFG[128];
    char* sA = sb;
    char* sB = sb + 64 * PITCH;
    const uint32_t smu = (uint32_t)__cvta_generic_to_shared(sb);
    const int t = threadIdx.x, l = t & 31, w = t >> 5;
    const int i0 = blockIdx.x * 64;

    if (t < 64) {
        int i = i0 + t;
        float mx = fdec(g_maxu);
        float es = g_es[i], ed = g_ed[i];
        float m = leakyf(es + mx);
        float A = __expf(es + mx - m);
        float B = __expf(0.2f * (es + mx) - m);
        g_AAh2[i] = packh2(A, A);
        g_BBh2[i] = packh2(B, B);
        sFG[t * 2]     = __expf(ed - mx);
        sFG[t * 2 + 1] = __expf(0.2f * (ed - mx));
    }

#pragma unroll
    for (int m = 0; m < 8; ++m) {
        int idx = t + m * 256, r = idx >> 5, c4 = idx & 31;
        float4 v = *(const float4*)(h + (size_t)(i0 + r) * FD + c4 * 4);
        uint2 pk; pk.x = packh2(v.x, v.y); pk.y = packh2(v.z, v.w);
        *(uint2*)(sA + r * PITCH + c4 * 8) = pk;
    }
#pragma unroll
    for (int m = 0; m < 8; ++m) {
        int idx = t + m * 256, r = idx >> 4, c8 = idx & 15;
        cp16(sB + r * PITCH + c8 * 16, g_W16T + r * FD + c8 * 8);
    }
    asm volatile("cp.async.commit_group;\ncp.async.wait_group 0;\n");
    __syncthreads();

    if (t < 16) {   // pack j4 for these 64 nodes
        uint4 v;
        v.x = packh2(sFG[t*8+0], sFG[t*8+2]);
        v.y = packh2(sFG[t*8+1], sFG[t*8+3]);
        v.z = packh2(sFG[t*8+4], sFG[t*8+6]);
        v.w = packh2(sFG[t*8+5], sFG[t*8+7]);
        g_j4[(i0 >> 2) + t] = v;
    }

    const int rg = w >> 2, nc = w & 3;
    float acc[2][4][4];
#pragma unroll
    for (int a = 0; a < 2; ++a)
#pragma unroll
        for (int n = 0; n < 4; ++n)
#pragma unroll
            for (int i = 0; i < 4; ++i) acc[a][n][i] = 0.f;
    uint32_t Pb0 = smu + (rg * 32 + (l & 15)) * PITCH + (l >> 4) * 16;
    uint32_t Pb1 = Pb0 + 16 * PITCH;
    uint32_t Wb  = smu + 64 * PITCH + (nc * 32 + (l & 7)) * PITCH + (l >> 3) * 16;
#pragma unroll
    for (int kc2 = 0; kc2 < 4; ++kc2) {
        uint32_t a0[4], a1[4], a2[4], a3[4];
        ldm4(a0, Pb0 + kc2 * 64); ldm4(a1, Pb0 + kc2 * 64 + 32);
        ldm4(a2, Pb1 + kc2 * 64); ldm4(a3, Pb1 + kc2 * 64 + 32);
#pragma unroll
        for (int nt = 0; nt < 4; ++nt) {
            uint32_t b[4];
            ldm4(b, Wb + nt * 8 * PITCH + kc2 * 64);
            mma16816(acc[0][nt], a0[0], a0[1], a0[2], a0[3], b[0], b[1]);
            mma16816(acc[0][nt], a1[0], a1[1], a1[2], a1[3], b[2], b[3]);
            mma16816(acc[1][nt], a2[0], a2[1], a2[2], a2[3], b[0], b[1]);
            mma16816(acc[1][nt], a3[0], a3[1], a3[2], a3[3], b[2], b[3]);
        }
    }
    __syncthreads();
    float (*T)[132] = reinterpret_cast<float(*)[132]>(sb);
#pragma unroll
    for (int a = 0; a < 2; ++a)
#pragma unroll
        for (int nt = 0; nt < 4; ++nt) {
            int row = rg * 32 + a * 16 + (l >> 2);
            int col = nc * 32 + nt * 8 + (l & 3) * 2;
            *(float2*)&T[row][col]     = make_float2(acc[a][nt][0], acc[a][nt][1]);
            *(float2*)&T[row + 8][col] = make_float2(acc[a][nt][2], acc[a][nt][3]);
        }
    __syncthreads();
    {
        int c = t >> 1, hf = t & 1;
#pragma unroll
        for (int g = 0; g < 2; ++g) {
            int r0 = hf * 32 + g * 16;
            uint4 pk, pk2;
            pk.x  = packh2(T[r0+0][c],  T[r0+1][c]);
            pk.y  = packh2(T[r0+2][c],  T[r0+3][c]);
            pk.z  = packh2(T[r0+4][c],  T[r0+5][c]);
            pk.w  = packh2(T[r0+6][c],  T[r0+7][c]);
            pk2.x = packh2(T[r0+8][c],  T[r0+9][c]);
            pk2.y = packh2(T[r0+10][c], T[r0+11][c]);
            pk2.z = packh2(T[r0+12][c], T[r0+13][c]);
            pk2.w = packh2(T[r0+14][c], T[r0+15][c]);
            *(uint4*)(g_WhT + (size_t)c * NN + i0 + r0)     = pk;
            *(uint4*)(g_WhT + (size_t)c * NN + i0 + r0 + 8) = pk2;
        }
    }
}

// ---- k_flash: pipelined, staggered, half2 P, fused combine ------------------
#define OFF_P0 0
#define OFF_P1 34816
#define OFF_W0 69632
#define OFF_W1 104448
#define OFF_LS 139264
#define SMEMSZ 139808
#define ONE2 0x3C003C00u

__global__ void __launch_bounds__(512) k_flash(const int* __restrict__ adj,
                                               float* __restrict__ out) {
    extern __shared__ __align__(16) char sm[];
    const uint32_t smu = (uint32_t)__cvta_generic_to_shared(sm);
    const int t = threadIdx.x, l = t & 31, w = t >> 5;
    const int ib = blockIdx.x >> 1, jhalf = blockIdx.x & 1;
    const int i0 = ib * 128, jbase = jhalf * 4096;
    const int cg = l;
    const int rb = w * 8;
    float* sLS = (float*)(sm + OFF_LS);
    int* sFlag = (int*)(sm + OFF_LS + 512);

    const int rg = w >> 2, nc = w & 3;
    const uint32_t Wcol = (uint32_t)((nc * 32 + (l & 7)) * PITCH + (l >> 3) * 16);
    const uint32_t Prow = (uint32_t)((rg * 32 + (l & 15)) * PITCH + (l >> 4) * 16);
    float acc[2][4][4];
#pragma unroll
    for (int a = 0; a < 2; ++a)
#pragma unroll
        for (int n = 0; n < 4; ++n)
#pragma unroll
            for (int i = 0; i < 4; ++i) acc[a][n][i] = 0.f;
    float acc_ls[2][4];
#pragma unroll
    for (int a = 0; a < 2; ++a)
#pragma unroll
        for (int i = 0; i < 4; ++i) acc_ls[a][i] = 0.f;

    uint32_t AAu[8], BBu[8];
#pragma unroll
    for (int r = 0; r < 8; ++r) {
        AAu[r] = g_AAh2[i0 + rb + r];
        BBu[r] = g_BBh2[i0 + rb + r];
    }

    auto issueW = [&](int buf, int jb) {
        const int j0 = jbase + jb * 128;
        char* Wt = sm + (buf ? OFF_W1 : OFF_W0);
#pragma unroll
        for (int mm = 0; mm < 4; ++mm) {
            int idx = t + mm * 512, f = idx >> 4, c8 = idx & 15;
            cp16(Wt + f * PITCH + c8 * 16, g_WhT + (size_t)f * NN + j0 + c8 * 8);
        }
    };

    issueW(0, 0);
    asm volatile("cp.async.commit_group;\n");

    uint4 j4 = g_j4[(jbase >> 2) + cg];
    int4 areg[8];
#pragma unroll
    for (int r = 0; r < 8; ++r)
        areg[r] = *(const int4*)(adj + (size_t)(i0 + rb + r) * NN + jbase + cg * 4);

    // P(0)
    {
        char* Pp = sm + OFF_P0 + rb * PITCH + cg * 8;
#pragma unroll
        for (int r = 0; r < 8; ++r) {
            int4 q = areg[r];
            uint32_t m01 = (uint32_t)q.x * 0x0000FFFFu + (uint32_t)q.y * 0xFFFF0000u;
            uint32_t m23 = (uint32_t)q.z * 0x0000FFFFu + (uint32_t)q.w * 0xFFFF0000u;
            uint32_t p01 = h2u(__hmax2(__hmul2(u2h(AAu[r]), u2h(j4.x)),
                                       __hmul2(u2h(BBu[r]), u2h(j4.y)))) & m01;
            uint32_t p23 = h2u(__hmax2(__hmul2(u2h(AAu[r]), u2h(j4.z)),
                                       __hmul2(u2h(BBu[r]), u2h(j4.w)))) & m23;
            uint2 pk; pk.x = p01; pk.y = p23;
            *(uint2*)(Pp + r * PITCH) = pk;
        }
        j4 = g_j4[((jbase + 128) >> 2) + cg];
#pragma unroll
        for (int r = 0; r < 8; ++r)
            areg[r] = *(const int4*)(adj + (size_t)(i0 + rb + r) * NN + jbase + 128 + cg * 4);
    }

    for (int jb = 0; jb < 32; ++jb) {
        const int buf = jb & 1;
        asm volatile("cp.async.wait_group 0;\n");
        __syncthreads();
        if (jb + 1 < 32) {
            issueW(buf ^ 1, jb + 1);
            asm volatile("cp.async.commit_group;\n");
        }

        auto doP = [&]() {
            if (jb + 1 >= 32) return;
            char* Pp = sm + (buf ? OFF_P0 : OFF_P1) + rb * PITCH + cg * 8;
#pragma unroll
            for (int r = 0; r < 8; ++r) {
                int4 q = areg[r];
                uint32_t m01 = (uint32_t)q.x * 0x0000FFFFu + (uint32_t)q.y * 0xFFFF0000u;
                uint32_t m23 = (uint32_t)q.z * 0x0000FFFFu + (uint32_t)q.w * 0xFFFF0000u;
                uint32_t p01 = h2u(__hmax2(__hmul2(u2h(AAu[r]), u2h(j4.x)),
                                           __hmul2(u2h(BBu[r]), u2h(j4.y)))) & m01;
                uint32_t p23 = h2u(__hmax2(__hmul2(u2h(AAu[r]), u2h(j4.z)),
                                           __hmul2(u2h(BBu[r]), u2h(j4.w)))) & m23;
                uint2 pk; pk.x = p01; pk.y = p23;
                *(uint2*)(Pp + r * PITCH) = pk;
            }
            if (jb + 2 < 32) {
                const int joff = jbase + (jb + 2) * 128;
                j4 = g_j4[(joff >> 2) + cg];
#pragma unroll
                for (int r = 0; r < 8; ++r)
                    areg[r] = *(const int4*)(adj + (size_t)(i0 + rb + r) * NN + joff + cg * 4);
            }
        };
        auto doMMA = [&]() {
            const uint32_t Pb0 = smu + (buf ? OFF_P1 : OFF_P0) + Prow;
            const uint32_t Pb1 = Pb0 + 16 * PITCH;
            const uint32_t Wb  = smu + (buf ? OFF_W1 : OFF_W0) + Wcol;
#pragma unroll
            for (int kc2 = 0; kc2 < 4; ++kc2) {
                uint32_t a0[4], a1[4], a2[4], a3[4];
                ldm4(a0, Pb0 + kc2 * 64); ldm4(a1, Pb0 + kc2 * 64 + 32);
                ldm4(a2, Pb1 + kc2 * 64); ldm4(a3, Pb1 + kc2 * 64 + 32);
#pragma unroll
                for (int nt = 0; nt < 4; ++nt) {
                    uint32_t b[4];
                    ldm4(b, Wb + nt * 8 * PITCH + kc2 * 64);
                    mma16816(acc[0][nt], a0[0], a0[1], a0[2], a0[3], b[0], b[1]);
                    mma16816(acc[0][nt], a1[0], a1[1], a1[2], a1[3], b[2], b[3]);
                    mma16816(acc[1][nt], a2[0], a2[1], a2[2], a2[3], b[0], b[1]);
                    mma16816(acc[1][nt], a3[0], a3[1], a3[2], a3[3], b[2], b[3]);
                }
                if (nc == 0) {   // row sums via ones-column
                    mma16816(acc_ls[0], a0[0], a0[1], a0[2], a0[3], ONE2, ONE2);
                    mma16816(acc_ls[0], a1[0], a1[1], a1[2], a1[3], ONE2, ONE2);
                    mma16816(acc_ls[1], a2[0], a2[1], a2[2], a2[3], ONE2, ONE2);
                    mma16816(acc_ls[1], a3[0], a3[1], a3[2], a3[3], ONE2, ONE2);
                }
            }
        };

        if (w & 1) { doMMA(); doP(); }
        else       { doP(); doMMA(); }
    }

    // ---- epilogue: sums to smem, partials to gmem, second CTA combines ------
    __syncthreads();
    if (nc == 0 && (l & 3) == 0) {
        int rl = rg * 32 + (l >> 2);
        sLS[rl]      = acc_ls[0][0];
        sLS[rl + 8]  = acc_ls[0][2];
        sLS[rl + 16] = acc_ls[1][0];
        sLS[rl + 24] = acc_ls[1][2];
    }
    __syncthreads();
    if (t < 128) g_lsp[jhalf * NN + i0 + t] = sLS[t];
#pragma unroll
    for (int a = 0; a < 2; ++a)
#pragma unroll
        for (int nt = 0; nt < 4; ++nt) {
            int row = i0 + rg * 32 + a * 16 + (l >> 2);
            int col = nc * 32 + nt * 8 + (l & 3) * 2;
            *(float2*)&g_part[((size_t)jhalf * NN + row) * FD + col] =
                make_float2(acc[a][nt][0], acc[a][nt][1]);
            *(float2*)&g_part[((size_t)jhalf * NN + row + 8) * FD + col] =
                make_float2(acc[a][nt][2], acc[a][nt][3]);
        }
    __threadfence();
    __syncthreads();
    if (t == 0) sFlag[0] = atomicAdd(&g_cnt[ib], 1);
    __syncthreads();
    if (sFlag[0] == 1) {
        __threadfence();
        const float* op = g_part + (size_t)(1 - jhalf) * NN * FD;
        const float* ol = g_lsp + (1 - jhalf) * NN;
        int rl = rg * 32 + (l >> 2);
        float invs[4];
        invs[0] = 1.f / (sLS[rl]      + ol[i0 + rl]);
        invs[1] = 1.f / (sLS[rl + 8]  + ol[i0 + rl + 8]);
        invs[2] = 1.f / (sLS[rl + 16] + ol[i0 + rl + 16]);
        invs[3] = 1.f / (sLS[rl + 24] + ol[i0 + rl + 24]);
#pragma unroll
        for (int a = 0; a < 2; ++a)
#pragma unroll
            for (int nt = 0; nt < 4; ++nt) {
                int row = i0 + rg * 32 + a * 16 + (l >> 2);
                int col = nc * 32 + nt * 8 + (l & 3) * 2;
                float2 o0 = *(const float2*)&op[(size_t)row * FD + col];
                float2 o1 = *(const float2*)&op[(size_t)(row + 8) * FD + col];
                *(float2*)&out[(size_t)row * FD + col] =
                    make_float2((acc[a][nt][0] + o0.x) * invs[a * 2],
                                (acc[a][nt][1] + o0.y) * invs[a * 2]);
                *(float2*)&out[(size_t)(row + 8) * FD + col] =
                    make_float2((acc[a][nt][2] + o1.x) * invs[a * 2 + 1],
                                (acc[a][nt][3] + o1.y) * invs[a * 2 + 1]);
            }
    }
}

// ---- launcher ---------------------------------------------------------------
extern "C" void kernel_launch(void* const* d_in, const int* in_sizes, int n_in,
                              void* d_out, int out_size) {
    const float* h   = (const float*)d_in[0];
    const int*   adj = (const int*)d_in[1];
    const float* W   = (const float*)d_in[2];
    const float* a   = (const float*)d_in[3];
    float* out = (float*)d_out;

    k_init<<<65, 256>>>(W, a);
    k_esd<<<NN / 8, 256>>>(h);
    k_wh16<<<NN / 64, 256>>>(h);
    cudaFuncSetAttribute(k_flash, cudaFuncAttributeMaxDynamicSharedMemorySize, SMEMSZ);
    k_flash<<<128, 512, SMEMSZ>>>(adj, out);
}

// round 16
// speedup vs baseline: 1.0372x; 1.0372x over previous
#include <cuda_runtime.h>
#include <cuda_fp16.h>
#include <cstdint>

#define NN 8192
#define FD 128
#define ALPHA 0.2f

__device__ float  g_Wa1[FD], g_Wa2[FD];
__device__ float  g_es[NN], g_ed[NN];
__device__ unsigned g_maxu;
__device__ uint32_t g_AAh2[NN], g_BBh2[NN];   // {A,A}, {B,B} half2
__device__ uint4  g_j4[NN / 4];               // {F01,G01,F23,G23} half2 x4
__device__ __half g_W16T[FD * FD];            // [fo][k]
__device__ __half g_WhT[(size_t)FD * NN];     // [f][node]
__device__ float  g_part[2u * NN * FD];
__device__ float  g_lsp[2 * NN];
__device__ int    g_cnt[64];

__device__ __forceinline__ float leakyf(float x) { return fmaxf(x, ALPHA * x); }
__device__ __forceinline__ uint32_t packh2(float x, float y) {
    __half2 h = __floats2half2_rn(x, y);
    return reinterpret_cast<uint32_t&>(h);
}
__device__ __forceinline__ __half2 u2h(uint32_t u) { return *reinterpret_cast<__half2*>(&u); }
__device__ __forceinline__ uint32_t h2u(__half2 h) { return *reinterpret_cast<uint32_t*>(&h); }
__device__ __forceinline__ void mma16816(float* c,
                                         uint32_t a0, uint32_t a1, uint32_t a2, uint32_t a3,
                                         uint32_t b0, uint32_t b1) {
    asm volatile(
        "mma.sync.aligned.m16n8k16.row.col.f32.f16.f16.f32 "
        "{%0,%1,%2,%3}, {%4,%5,%6,%7}, {%8,%9}, {%0,%1,%2,%3};\n"
        : "+f"(c[0]), "+f"(c[1]), "+f"(c[2]), "+f"(c[3])
        : "r"(a0), "r"(a1), "r"(a2), "r"(a3), "r"(b0), "r"(b1));
}
__device__ __forceinline__ void cp16(void* s, const void* g) {
    unsigned sa = (unsigned)__cvta_generic_to_shared(s);
    asm volatile("cp.async.cg.shared.global [%0], [%1], 16;\n" :: "r"(sa), "l"(g));
}
__device__ __forceinline__ void ldm4(uint32_t* r, uint32_t a) {
    asm volatile("ldmatrix.sync.aligned.m8n8.x4.shared.b16 {%0,%1,%2,%3}, [%4];"
                 : "=r"(r[0]), "=r"(r[1]), "=r"(r[2]), "=r"(r[3]) : "r"(a));
}
__device__ __forceinline__ unsigned fenc(float f) {
    unsigned b = __float_as_uint(f);
    return (b & 0x80000000u) ? ~b : (b | 0x80000000u);
}
__device__ __forceinline__ float fdec(unsigned k) {
    unsigned b = (k & 0x80000000u) ? (k & 0x7FFFFFFFu) : ~k;
    return __uint_as_float(b);
}

// ---- k_init: Wa1/Wa2, W fp16 transpose, reset max + counters ----------------
__global__ void k_init(const float* __restrict__ W, const float* __restrict__ a) {
    if (blockIdx.x == 0) {
        int i = threadIdx.x;
        if (i == 0) g_maxu = 0u;
        if (i < 64) g_cnt[i] = 0;
        if (i < FD) {
            const float* wr = W + i * FD;
            float s1 = 0.f, s2 = 0.f;
#pragma unroll 8
            for (int j = 0; j < FD; ++j) {
                float w = wr[j];
                s1 += w * a[j];
                s2 += w * a[FD + j];
            }
            g_Wa1[i] = s1; g_Wa2[i] = s2;
        }
    } else {
        int n = (blockIdx.x - 1) * 256 + threadIdx.x;
        int k = n >> 7, fo = n & 127;
        g_W16T[fo * FD + k] = __float2half(W[n]);
    }
}

// ---- k_esd: es/ed exact fp32 GEMV + fused global max ------------------------
__global__ void __launch_bounds__(256) k_esd(const float* __restrict__ h) {
    __shared__ float s1[FD], s2[FD];
    int t = threadIdx.x, l = t & 31, w = t >> 5;
    if (t < FD) { s1[t] = g_Wa1[t]; s2[t] = g_Wa2[t]; }
    __syncthreads();
    int i = blockIdx.x * 8 + w;
    float4 hv0 = *(const float4*)(h + (size_t)i * FD + l * 4);
    float e1 = hv0.x*s1[l*4] + hv0.y*s1[l*4+1] + hv0.z*s1[l*4+2] + hv0.w*s1[l*4+3];
    float e2 = hv0.x*s2[l*4] + hv0.y*s2[l*4+1] + hv0.z*s2[l*4+2] + hv0.w*s2[l*4+3];
#pragma unroll
    for (int o = 16; o; o >>= 1) {
        e1 += __shfl_xor_sync(0xffffffffu, e1, o);
        e2 += __shfl_xor_sync(0xffffffffu, e2, o);
    }
    if (l == 0) {
        g_es[i] = e1; g_ed[i] = e2;
        atomicMax(&g_maxu, fenc(e2));
    }
}

// ---- k_wh16: fused pre (AA/BB/j4) + WhT = (h@W)^T fp16 via HMMA -------------
#define PITCH 272
__global__ void __launch_bounds__(256) k_wh16(const float* __restrict__ h) {
    __shared__ __align__(16) char sb[128 * PITCH + 64 * PITCH];
    __shared__ float sFG[128];
    char* sA = sb;
    char* sB = sb + 64 * PITCH;
    const uint32_t smu = (uint32_t)__cvta_generic_to_shared(sb);
    const int t = threadIdx.x, l = t & 31, w = t >> 5;
    const int i0 = blockIdx.x * 64;

    if (t < 64) {
        int i = i0 + t;
        float mx = fdec(g_maxu);
        float es = g_es[i], ed = g_ed[i];
        float m = leakyf(es + mx);
        float A = __expf(es + mx - m);
        float B = __expf(0.2f * (es + mx) - m);
        g_AAh2[i] = packh2(A, A);
        g_BBh2[i] = packh2(B, B);
        sFG[t * 2]     = __expf(ed - mx);
        sFG[t * 2 + 1] = __expf(0.2f * (ed - mx));
    }

#pragma unroll
    for (int m = 0; m < 8; ++m) {
        int idx = t + m * 256, r = idx >> 5, c4 = idx & 31;
        float4 v = *(const float4*)(h + (size_t)(i0 + r) * FD + c4 * 4);
        uint2 pk; pk.x = packh2(v.x, v.y); pk.y = packh2(v.z, v.w);
        *(uint2*)(sA + r * PITCH + c4 * 8) = pk;
    }
#pragma unroll
    for (int m = 0; m < 8; ++m) {
        int idx = t + m * 256, r = idx >> 4, c8 = idx & 15;
        cp16(sB + r * PITCH + c8 * 16, g_W16T + r * FD + c8 * 8);
    }
    asm volatile("cp.async.commit_group;\ncp.async.wait_group 0;\n");
    __syncthreads();

    if (t < 16) {
        uint4 v;
        v.x = packh2(sFG[t*8+0], sFG[t*8+2]);
        v.y = packh2(sFG[t*8+1], sFG[t*8+3]);
        v.z = packh2(sFG[t*8+4], sFG[t*8+6]);
        v.w = packh2(sFG[t*8+5], sFG[t*8+7]);
        g_j4[(i0 >> 2) + t] = v;
    }

    const int rg = w >> 2, nc = w & 3;
    float acc[2][4][4];
#pragma unroll
    for (int a = 0; a < 2; ++a)
#pragma unroll
        for (int n = 0; n < 4; ++n)
#pragma unroll
            for (int i = 0; i < 4; ++i) acc[a][n][i] = 0.f;
    uint32_t Pb0 = smu + (rg * 32 + (l & 15)) * PITCH + (l >> 4) * 16;
    uint32_t Pb1 = Pb0 + 16 * PITCH;
    uint32_t Wb  = smu + 64 * PITCH + (nc * 32 + (l & 7)) * PITCH + (l >> 3) * 16;
#pragma unroll
    for (int kc2 = 0; kc2 < 4; ++kc2) {
        uint32_t a0[4], a1[4], a2[4], a3[4];
        ldm4(a0, Pb0 + kc2 * 64); ldm4(a1, Pb0 + kc2 * 64 + 32);
        ldm4(a2, Pb1 + kc2 * 64); ldm4(a3, Pb1 + kc2 * 64 + 32);
#pragma unroll
        for (int nt = 0; nt < 4; ++nt) {
            uint32_t b[4];
            ldm4(b, Wb + nt * 8 * PITCH + kc2 * 64);
            mma16816(acc[0][nt], a0[0], a0[1], a0[2], a0[3], b[0], b[1]);
            mma16816(acc[0][nt], a1[0], a1[1], a1[2], a1[3], b[2], b[3]);
            mma16816(acc[1][nt], a2[0], a2[1], a2[2], a2[3], b[0], b[1]);
            mma16816(acc[1][nt], a3[0], a3[1], a3[2], a3[3], b[2], b[3]);
        }
    }
    __syncthreads();
    float (*T)[132] = reinterpret_cast<float(*)[132]>(sb);
#pragma unroll
    for (int a = 0; a < 2; ++a)
#pragma unroll
        for (int nt = 0; nt < 4; ++nt) {
            int row = rg * 32 + a * 16 + (l >> 2);
            int col = nc * 32 + nt * 8 + (l & 3) * 2;
            *(float2*)&T[row][col]     = make_float2(acc[a][nt][0], acc[a][nt][1]);
            *(float2*)&T[row + 8][col] = make_float2(acc[a][nt][2], acc[a][nt][3]);
        }
    __syncthreads();
    {
        int c = t >> 1, hf = t & 1;
#pragma unroll
        for (int g = 0; g < 2; ++g) {
            int r0 = hf * 32 + g * 16;
            uint4 pk, pk2;
            pk.x  = packh2(T[r0+0][c],  T[r0+1][c]);
            pk.y  = packh2(T[r0+2][c],  T[r0+3][c]);
            pk.z  = packh2(T[r0+4][c],  T[r0+5][c]);
            pk.w  = packh2(T[r0+6][c],  T[r0+7][c]);
            pk2.x = packh2(T[r0+8][c],  T[r0+9][c]);
            pk2.y = packh2(T[r0+10][c], T[r0+11][c]);
            pk2.z = packh2(T[r0+12][c], T[r0+13][c]);
            pk2.w = packh2(T[r0+14][c], T[r0+15][c]);
            *(uint4*)(g_WhT + (size_t)c * NN + i0 + r0)     = pk;
            *(uint4*)(g_WhT + (size_t)c * NN + i0 + r0 + 8) = pk2;
        }
    }
}

// ---- k_flash: pipelined, staggered, half2 P, balanced ones-MMA sums ---------
#define OFF_P0 0
#define OFF_P1 34816
#define OFF_W0 69632
#define OFF_W1 104448
#define OFF_LS 139264
#define SMEMSZ 141376
#define ONE2 0x3C003C00u

__global__ void __launch_bounds__(512) k_flash(const int* __restrict__ adj,
                                               float* __restrict__ out) {
    extern __shared__ __align__(16) char sm[];
    const uint32_t smu = (uint32_t)__cvta_generic_to_shared(sm);
    const int t = threadIdx.x, l = t & 31, w = t >> 5;
    const int ib = blockIdx.x >> 1, jhalf = blockIdx.x & 1;
    const int i0 = ib * 128, jbase = jhalf * 4096;
    const int cg = l;
    const int rb = w * 8;
    float* sLS = (float*)(sm + OFF_LS);            // [4][128] per-nc partials
    int* sFlag = (int*)(sm + OFF_LS + 2048);

    const int rg = w >> 2, nc = w & 3;
    const uint32_t Wcol = (uint32_t)((nc * 32 + (l & 7)) * PITCH + (l >> 3) * 16);
    const uint32_t Prow = (uint32_t)((rg * 32 + (l & 15)) * PITCH + (l >> 4) * 16);
    float acc[2][4][4];
#pragma unroll
    for (int a = 0; a < 2; ++a)
#pragma unroll
        for (int n = 0; n < 4; ++n)
#pragma unroll
            for (int i = 0; i < 4; ++i) acc[a][n][i] = 0.f;
    float acc_ls[2][4];
#pragma unroll
    for (int a = 0; a < 2; ++a)
#pragma unroll
        for (int i = 0; i < 4; ++i) acc_ls[a][i] = 0.f;

    uint32_t AAu[8], BBu[8];
#pragma unroll
    for (int r = 0; r < 8; ++r) {
        AAu[r] = g_AAh2[i0 + rb + r];
        BBu[r] = g_BBh2[i0 + rb + r];
    }

    auto issueW = [&](int buf, int jb) {
        const int j0 = jbase + jb * 128;
        char* Wt = sm + (buf ? OFF_W1 : OFF_W0);
#pragma unroll
        for (int mm = 0; mm < 4; ++mm) {
            int idx = t + mm * 512, f = idx >> 4, c8 = idx & 15;
            cp16(Wt + f * PITCH + c8 * 16, g_WhT + (size_t)f * NN + j0 + c8 * 8);
        }
    };

    issueW(0, 0);
    asm volatile("cp.async.commit_group;\n");

    uint4 j4 = g_j4[(jbase >> 2) + cg];
    int4 areg[8];
#pragma unroll
    for (int r = 0; r < 8; ++r)
        areg[r] = *(const int4*)(adj + (size_t)(i0 + rb + r) * NN + jbase + cg * 4);

    // P(0)
    {
        char* Pp = sm + OFF_P0 + rb * PITCH + cg * 8;
#pragma unroll
        for (int r = 0; r < 8; ++r) {
            int4 q = areg[r];
            uint32_t m01 = (uint32_t)q.x * 0x0000FFFFu + (uint32_t)q.y * 0xFFFF0000u;
            uint32_t m23 = (uint32_t)q.z * 0x0000FFFFu + (uint32_t)q.w * 0xFFFF0000u;
            uint32_t p01 = h2u(__hmax2(__hmul2(u2h(AAu[r]), u2h(j4.x)),
                                       __hmul2(u2h(BBu[r]), u2h(j4.y)))) & m01;
            uint32_t p23 = h2u(__hmax2(__hmul2(u2h(AAu[r]), u2h(j4.z)),
                                       __hmul2(u2h(BBu[r]), u2h(j4.w)))) & m23;
            uint2 pk; pk.x = p01; pk.y = p23;
            *(uint2*)(Pp + r * PITCH) = pk;
        }
        j4 = g_j4[((jbase + 128) >> 2) + cg];
#pragma unroll
        for (int r = 0; r < 8; ++r)
            areg[r] = *(const int4*)(adj + (size_t)(i0 + rb + r) * NN + jbase + 128 + cg * 4);
    }

    for (int jb = 0; jb < 32; ++jb) {
        const int buf = jb & 1;
        asm volatile("cp.async.wait_group 0;\n");
        __syncthreads();
        if (jb + 1 < 32) {
            issueW(buf ^ 1, jb + 1);
            asm volatile("cp.async.commit_group;\n");
        }

        auto doP = [&]() {
            if (jb + 1 >= 32) return;
            char* Pp = sm + (buf ? OFF_P0 : OFF_P1) + rb * PITCH + cg * 8;
#pragma unroll
            for (int r = 0; r < 8; ++r) {
                int4 q = areg[r];
                uint32_t m01 = (uint32_t)q.x * 0x0000FFFFu + (uint32_t)q.y * 0xFFFF0000u;
                uint32_t m23 = (uint32_t)q.z * 0x0000FFFFu + (uint32_t)q.w * 0xFFFF0000u;
                uint32_t p01 = h2u(__hmax2(__hmul2(u2h(AAu[r]), u2h(j4.x)),
                                           __hmul2(u2h(BBu[r]), u2h(j4.y)))) & m01;
                uint32_t p23 = h2u(__hmax2(__hmul2(u2h(AAu[r]), u2h(j4.z)),
                                           __hmul2(u2h(BBu[r]), u2h(j4.w)))) & m23;
                uint2 pk; pk.x = p01; pk.y = p23;
                *(uint2*)(Pp + r * PITCH) = pk;
            }
            if (jb + 2 < 32) {
                const int joff = jbase + (jb + 2) * 128;
                j4 = g_j4[(joff >> 2) + cg];
#pragma unroll
                for (int r = 0; r < 8; ++r)
                    areg[r] = *(const int4*)(adj + (size_t)(i0 + rb + r) * NN + joff + cg * 4);
            }
        };
        auto doMMA = [&]() {
            const uint32_t Pb0 = smu + (buf ? OFF_P1 : OFF_P0) + Prow;
            const uint32_t Pb1 = Pb0 + 16 * PITCH;
            const uint32_t Wb  = smu + (buf ? OFF_W1 : OFF_W0) + Wcol;
#pragma unroll
            for (int kc2 = 0; kc2 < 4; ++kc2) {
                uint32_t a0[4], a1[4], a2[4], a3[4];
                ldm4(a0, Pb0 + kc2 * 64); ldm4(a1, Pb0 + kc2 * 64 + 32);
                ldm4(a2, Pb1 + kc2 * 64); ldm4(a3, Pb1 + kc2 * 64 + 32);
#pragma unroll
                for (int nt = 0; nt < 4; ++nt) {
                    uint32_t b[4];
                    ldm4(b, Wb + nt * 8 * PITCH + kc2 * 64);
                    mma16816(acc[0][nt], a0[0], a0[1], a0[2], a0[3], b[0], b[1]);
                    mma16816(acc[0][nt], a1[0], a1[1], a1[2], a1[3], b[2], b[3]);
                    mma16816(acc[1][nt], a2[0], a2[1], a2[2], a2[3], b[0], b[1]);
                    mma16816(acc[1][nt], a3[0], a3[1], a3[2], a3[3], b[2], b[3]);
                }
                if (nc == kc2) {   // balanced ones-column row sums (K-quarter)
                    mma16816(acc_ls[0], a0[0], a0[1], a0[2], a0[3], ONE2, ONE2);
                    mma16816(acc_ls[0], a1[0], a1[1], a1[2], a1[3], ONE2, ONE2);
                    mma16816(acc_ls[1], a2[0], a2[1], a2[2], a2[3], ONE2, ONE2);
                    mma16816(acc_ls[1], a3[0], a3[1], a3[2], a3[3], ONE2, ONE2);
                }
            }
        };

        if (w & 1) { doMMA(); doP(); }
        else       { doP(); doMMA(); }
    }

    // ---- epilogue: reduce per-nc partial sums, store partials, combine ------
    __syncthreads();
    if ((l & 3) == 0) {
        int rl = rg * 32 + (l >> 2);
        float* dst = sLS + nc * 128;
        dst[rl]      = acc_ls[0][0];
        dst[rl + 8]  = acc_ls[0][2];
        dst[rl + 16] = acc_ls[1][0];
        dst[rl + 24] = acc_ls[1][2];
    }
    __syncthreads();
    if (t < 128) {
        float s = sLS[t] + sLS[128 + t] + sLS[256 + t] + sLS[384 + t];
        sLS[t] = s;
        g_lsp[jhalf * NN + i0 + t] = s;
    }
#pragma unroll
    for (int a = 0; a < 2; ++a)
#pragma unroll
        for (int nt = 0; nt < 4; ++nt) {
            int row = i0 + rg * 32 + a * 16 + (l >> 2);
            int col = nc * 32 + nt * 8 + (l & 3) * 2;
            *(float2*)&g_part[((size_t)jhalf * NN + row) * FD + col] =
                make_float2(acc[a][nt][0], acc[a][nt][1]);
            *(float2*)&g_part[((size_t)jhalf * NN + row + 8) * FD + col] =
                make_float2(acc[a][nt][2], acc[a][nt][3]);
        }
    __threadfence();
    __syncthreads();
    if (t == 0) sFlag[0] = atomicAdd(&g_cnt[ib], 1);
    __syncthreads();
    if (sFlag[0] == 1) {
        __threadfence();
        const float* op = g_part + (size_t)(1 - jhalf) * NN * FD;
        const float* ol = g_lsp + (1 - jhalf) * NN;
        int rl = rg * 32 + (l >> 2);
        float invs[4];
        invs[0] = 1.f / (sLS[rl]      + ol[i0 + rl]);
        invs[1] = 1.f / (sLS[rl + 8]  + ol[i0 + rl + 8]);
        invs[2] = 1.f / (sLS[rl + 16] + ol[i0 + rl + 16]);
        invs[3] = 1.f / (sLS[rl + 24] + ol[i0 + rl + 24]);
#pragma unroll
        for (int a = 0; a < 2; ++a)
#pragma unroll
            for (int nt = 0; nt < 4; ++nt) {
                int row = i0 + rg * 32 + a * 16 + (l >> 2);
                int col = nc * 32 + nt * 8 + (l & 3) * 2;
                float2 o0 = *(const float2*)&op[(size_t)row * FD + col];
                float2 o1 = *(const float2*)&op[(size_t)(row + 8) * FD + col];
                *(float2*)&out[(size_t)row * FD + col] =
                    make_float2((acc[a][nt][0] + o0.x) * invs[a * 2],
                                (acc[a][nt][1] + o0.y) * invs[a * 2]);
                *(float2*)&out[(size_t)(row + 8) * FD + col] =
                    make_float2((acc[a][nt][2] + o1.x) * invs[a * 2 + 1],
                                (acc[a][nt][3] + o1.y) * invs[a * 2 + 1]);
            }
    }
}

// ---- launcher ---------------------------------------------------------------
extern "C" void kernel_launch(void* const* d_in, const int* in_sizes, int n_in,
                              void* d_out, int out_size) {
    const float* h   = (const float*)d_in[0];
    const int*   adj = (const int*)d_in[1];
    const float* W   = (const float*)d_in[2];
    const float* a   = (const float*)d_in[3];
    float* out = (float*)d_out;

    k_init<<<65, 256>>>(W, a);
    k_esd<<<NN / 8, 256>>>(h);
    k_wh16<<<NN / 64, 256>>>(h);
    cudaFuncSetAttribute(k_flash, cudaFuncAttributeMaxDynamicSharedMemorySize, SMEMSZ);
    k_flash<<<128, 512, SMEMSZ>>>(adj, out);
}